// round 4
// baseline (speedup 1.0000x reference)
#include <cuda_runtime.h>
#include <cuda_fp16.h>
#include <math.h>
#include <stdint.h>

#define BATCH 16
#define SEQT  256
#define STATE 1024
#define VOCAB 32000
#define MROWS (SEQT*BATCH)          /* 4096 */
#define LOGITS ((size_t)BATCH*SEQT*VOCAB)
#define NBLK 128

// ------------------------- static device scratch -------------------------
__device__ __half g_WxT[2*3*1024*1024];        // [(j*3+g)*1024 + c][k]  x-part W^T
__device__ __half g_WoT[(size_t)VOCAB*1024];   // [v][k]
__device__ __half g_X0 [(size_t)MROWS*1024];   // embeddings fp16, row = t*16+b
__device__ __half g_Hall[2*(size_t)MROWS*1024];// hidden states per layer, row = t*16+b
__device__ float  g_G  [(size_t)SEQT*3*BATCH*1024]; // [t][gate][c][b]
// batch-minor per-step state
__device__ float  g_hfT[1024*16];              // [c][b] fp32 h
__device__ float  g_zT [1024*16];              // [c][b]
__device__ __half g_hT [1024*16];              // [k/2][b][2] fp16 h  (uint32 = (h[b][2k],h[b][2k+1]))
__device__ __half g_rhT[1024*16];              // same layout, r*h
// mma-fragment-packed recurrent weights
__device__ uint4  gFragA[(size_t)2*NBLK*8*8*32];   // [j][bid128][kh8][ks8][lane32] : z|r
__device__ uint4  gFragB[(size_t)2*64*8*8*32];     // [j][bid64][kh8][ks8][lane32] : n
// barrier flags (monotonic across launches/replays)
__device__ volatile unsigned g_flag[NBLK];

// ------------------------- small helpers -------------------------
__device__ __forceinline__ uint32_t smem_u32(const void* p){
    return (uint32_t)__cvta_generic_to_shared(p);
}
__device__ __forceinline__ void ldsm_x4(uint32_t* r, uint32_t a){
    asm volatile("ldmatrix.sync.aligned.m8n8.x4.shared.b16 {%0,%1,%2,%3},[%4];"
        : "=r"(r[0]),"=r"(r[1]),"=r"(r[2]),"=r"(r[3]) : "r"(a));
}
__device__ __forceinline__ void mma16816(float* c, const uint32_t* a, uint32_t b0, uint32_t b1){
    asm volatile(
      "mma.sync.aligned.m16n8k16.row.col.f32.f16.f16.f32 "
      "{%0,%1,%2,%3},{%4,%5,%6,%7},{%8,%9},{%0,%1,%2,%3};"
      : "+f"(c[0]),"+f"(c[1]),"+f"(c[2]),"+f"(c[3])
      : "r"(a[0]),"r"(a[1]),"r"(a[2]),"r"(a[3]),"r"(b0),"r"(b1));
}
__device__ __forceinline__ void cp16(void* s, const void* g){
    asm volatile("cp.async.cg.shared.global [%0],[%1],16;" :: "r"(smem_u32(s)), "l"(g));
}
#define CP_COMMIT() asm volatile("cp.async.commit_group;")
#define CP_WAIT1()  asm volatile("cp.async.wait_group 1;")
#define CP_WAIT0()  asm volatile("cp.async.wait_group 0;")

// symmetric all-poll-all grid barrier
__device__ __forceinline__ void gridbar(unsigned target){
    __threadfence();                 // release: my stores -> visible before flag
    __syncthreads();
    if (threadIdx.x == 0) g_flag[blockIdx.x] = target;
    unsigned t = threadIdx.x;
    if (t < NBLK) while (g_flag[t] < target) { }
    __syncthreads();
    if (threadIdx.x == 0) __threadfence();   // acquire + L1D invalidate
    __syncthreads();
}

// ------------------------- weight prep -------------------------
__global__ void wconv_gate(const float* __restrict__ Wz, const float* __restrict__ Wr,
                           const float* __restrict__ Wn){
    int jg = blockIdx.z; int g = jg % 3; int j = jg / 3;
    const float* W = (g==0?Wz:(g==1?Wr:Wn)) + (size_t)j*2048*1024;
    __shared__ float tile[32][33];
    int k0 = blockIdx.x*32, c0 = blockIdx.y*32;
    int tx = threadIdx.x, ty = threadIdx.y;
    for (int i=ty;i<32;i+=8)
        tile[i][tx] = W[(size_t)(k0+i)*1024 + c0 + tx];
    __syncthreads();
    for (int i=ty;i<32;i+=8)
        g_WxT[((size_t)(j*3+g)*1024 + c0 + i)*1024 + k0 + tx] = __float2half(tile[tx][i]);
}

__global__ void wconv_o(const float* __restrict__ Wo){
    __shared__ float tile[32][33];
    int v0 = blockIdx.x*32, k0 = blockIdx.y*32;
    int tx = threadIdx.x, ty = threadIdx.y;
    for (int i=ty;i<32;i+=8)
        tile[i][tx] = Wo[(size_t)(k0+i)*VOCAB + v0 + tx];
    __syncthreads();
    for (int i=ty;i<32;i+=8)
        g_WoT[(size_t)(v0+i)*1024 + k0 + tx] = __float2half(tile[tx][i]);
}

// h-part gate weights -> mma A-fragment order
__global__ void repackA(const float* __restrict__ Wz, const float* __restrict__ Wr){
    int bid = blockIdx.x, kh = blockIdx.y, j = blockIdx.z;
    int tid = threadIdx.x;
    int ks = tid >> 5, lane = tid & 31;
    int r = lane >> 2, q = (lane & 3)*2;
    int gate = bid >> 6;
    int n0 = (bid & 63)*16;
    const float* W = (gate ? Wr : Wz) + (size_t)j*2048*1024;
    int k0 = kh*128 + ks*16;
    size_t rb = (size_t)(1024 + k0 + q)*1024 + n0 + r;
    uint4 o; __half2 t;
    t = __floats2half2_rn(W[rb],              W[rb + 1024]);         o.x = *(uint32_t*)&t;
    t = __floats2half2_rn(W[rb + 8],          W[rb + 1024 + 8]);     o.y = *(uint32_t*)&t;
    t = __floats2half2_rn(W[rb + 8*1024],     W[rb + 9*1024]);       o.z = *(uint32_t*)&t;
    t = __floats2half2_rn(W[rb + 8*1024 + 8], W[rb + 9*1024 + 8]);   o.w = *(uint32_t*)&t;
    gFragA[((((size_t)j*NBLK + bid)*8 + kh)*8 + ks)*32 + lane] = o;
}

__global__ void repackB(const float* __restrict__ Wn){
    int bid = blockIdx.x, kh = blockIdx.y, j = blockIdx.z;
    int tid = threadIdx.x;
    int ks = tid >> 5, lane = tid & 31;
    int r = lane >> 2, q = (lane & 3)*2;
    int n0 = bid*16;
    const float* W = Wn + (size_t)j*2048*1024;
    int k0 = kh*128 + ks*16;
    size_t rb = (size_t)(1024 + k0 + q)*1024 + n0 + r;
    uint4 o; __half2 t;
    t = __floats2half2_rn(W[rb],              W[rb + 1024]);         o.x = *(uint32_t*)&t;
    t = __floats2half2_rn(W[rb + 8],          W[rb + 1024 + 8]);     o.y = *(uint32_t*)&t;
    t = __floats2half2_rn(W[rb + 8*1024],     W[rb + 9*1024]);       o.z = *(uint32_t*)&t;
    t = __floats2half2_rn(W[rb + 8*1024 + 8], W[rb + 9*1024 + 8]);   o.w = *(uint32_t*)&t;
    gFragB[((((size_t)j*64 + bid)*8 + kh)*8 + ks)*32 + lane] = o;
}

__global__ void gather_emb(const int* __restrict__ x, const float* __restrict__ emb){
    int m = blockIdx.x;                 // t*16+b
    int t = m >> 4, b = m & 15;
    int tok = x[b*SEQT + t];
    float4 v = ((const float4*)(emb + (size_t)tok*1024))[threadIdx.x];
    __half2 h0 = __floats2half2_rn(v.x, v.y);
    __half2 h1 = __floats2half2_rn(v.z, v.w);
    size_t o = (size_t)m*1024 + threadIdx.x*4;
    *(__half2*)&g_X0[o]   = h0;
    *(__half2*)&g_X0[o+2] = h1;
}

// ------------------------- tensor-core GEMM (128x128x32 tiles) -------------------------
template<int MODE>
__global__ void __launch_bounds__(256) gemm_tc(
    int asel, int jl,
    const float* __restrict__ bias0, const float* __restrict__ bias1,
    const float* __restrict__ bias2, float* __restrict__ Cext)
{
    const __half* A = (asel==0) ? g_X0 : g_Hall + (size_t)(asel-1)*MROWS*1024;
    const __half* BT = (MODE==0) ? g_WxT + (size_t)jl*3*1024*1024 : g_WoT;

    __shared__ __half As[2][128][40];
    __shared__ __half Bs[2][128][40];

    const int tid = threadIdx.x;
    const int wid = tid >> 5, lane = tid & 31;
    const int wm = wid >> 2, wn = wid & 3;
    const int bm = blockIdx.y*128, bn = blockIdx.x*128;

    float acc[4][4][4];
    #pragma unroll
    for(int a=0;a<4;a++)
      #pragma unroll
      for(int b=0;b<4;b++){acc[a][b][0]=0;acc[a][b][1]=0;acc[a][b][2]=0;acc[a][b][3]=0;}

    #define GLOAD(buf,kc) do{                                                    \
        _Pragma("unroll")                                                        \
        for(int i=0;i<2;i++){                                                    \
            int cch = tid + i*256;                                               \
            int row = cch>>2, koff=(cch&3)*8;                                    \
            cp16(&As[buf][row][koff], A  + (size_t)(bm+row)*1024 + (kc)*32 + koff); \
            cp16(&Bs[buf][row][koff], BT + (size_t)(bn+row)*1024 + (kc)*32 + koff); \
        } }while(0)

    GLOAD(0,0); CP_COMMIT();

    for (int kc=0; kc<32; kc++){
        int buf = kc & 1;
        if (kc+1 < 32){ GLOAD(buf^1, kc+1); CP_COMMIT(); CP_WAIT1(); }
        else { CP_WAIT0(); }
        __syncthreads();

        #pragma unroll
        for(int ks=0;ks<2;ks++){
            uint32_t af[4][4];
            const int g = lane >> 3;
            #pragma unroll
            for(int mt=0;mt<4;mt++){
                int rr = wm*64 + mt*16 + ((g&1)<<3) + (lane&7);
                int kk = ks*16 + ((g>>1)<<3);
                ldsm_x4(af[mt], smem_u32(&As[buf][rr][kk]));
            }
            uint32_t bf[2][4];
            #pragma unroll
            for(int bt=0;bt<2;bt++){
                int rr = wn*32 + bt*16 + ((g>>1)<<3) + (lane&7);
                int kk = ks*16 + ((g&1)<<3);
                ldsm_x4(bf[bt], smem_u32(&Bs[buf][rr][kk]));
            }
            #pragma unroll
            for(int mt=0;mt<4;mt++)
              #pragma unroll
              for(int bt=0;bt<2;bt++){
                mma16816(acc[mt][bt*2+0], af[mt], bf[bt][0], bf[bt][1]);
                mma16816(acc[mt][bt*2+1], af[mt], bf[bt][2], bf[bt][3]);
              }
        }
        __syncthreads();
    }
    #undef GLOAD

    #pragma unroll
    for(int mt=0;mt<4;mt++){
        int mbase = bm + wm*64 + mt*16 + (lane>>2);
        #pragma unroll
        for(int nt=0;nt<4;nt++){
            int n = bn + wn*32 + nt*8 + (lane&3)*2;
            #pragma unroll
            for(int half_=0;half_<2;half_++){
                int m = mbase + half_*8;
                float v0 = acc[mt][nt][half_*2+0];
                float v1 = acc[mt][nt][half_*2+1];
                int tt = m>>4, b = m&15;
                if (MODE==0){
                    int g = n>>10, c = n&1023;
                    const float* bp = (g==0)?bias0:((g==1)?bias1:bias2);
                    size_t o = (size_t)tt*49152 + (size_t)g*16384 + (size_t)c*16 + b;
                    g_G[o]    = v0 + bp[jl*1024+c];
                    g_G[o+16] = v1 + bp[jl*1024+c+1];
                } else {
                    size_t o = ((size_t)b*SEQT + tt)*VOCAB + n;
                    float2 out; out.x = v0 + bias0[n]; out.y = v1 + bias0[n+1];
                    *(float2*)&Cext[o] = out;
                }
            }
        }
    }
}

// ------------------------- persistent recurrence (one layer) -------------------------
// 128 blocks x 256 threads. Phase A: blocks 0-63 => z cols bid*16.., 64-127 => r cols.
// Phase B: blocks 0-63 => n cols bid*16... Weights live in registers.
__global__ void __launch_bounds__(256) recur(int jl, float* __restrict__ hfin){
    const int tid = threadIdx.x, bid = blockIdx.x;
    const int wid = tid>>5, lane = tid&31;
    const int r = lane>>2, q = (lane&3)*2;
    __shared__ float red[8][16][17];

    unsigned base = g_flag[bid];   // stable: equals final target of previous launch
    __half* Hout = g_Hall + (size_t)jl*MROWS*1024;

    // preload recurrent weight fragments into registers
    const uint4* fa = gFragA + (((size_t)jl*NBLK + bid)*8 + wid)*8*32;
    uint4 wA[8];
    #pragma unroll
    for(int ks=0;ks<8;ks++) wA[ks] = fa[ks*32 + lane];
    uint4 wB[8];
    if (bid < 64){
        const uint4* fb = gFragB + (((size_t)jl*64 + bid)*8 + wid)*8*32;
        #pragma unroll
        for(int ks=0;ks<8;ks++) wB[ks] = fb[ks*32 + lane];
    }

    { int idx = bid*256 + tid;
      if (idx < 16384){ g_hfT[idx] = 0.f; g_hT[idx] = __float2half(0.f); } }
    unsigned nb = 1;
    gridbar(base + nb++);

    const uint32_t* h2  = (const uint32_t*)g_hT;
    const uint32_t* rh2 = (const uint32_t*)g_rhT;

    for (int t=0; t<SEQT; t++){
        const float* Gt = g_G + (size_t)t*49152;
        // ---------------- phase A : z (bid<64) / r (bid>=64) ----------------
        {
            float acc[2][4];
            #pragma unroll
            for(int b=0;b<2;b++){acc[b][0]=0;acc[b][1]=0;acc[b][2]=0;acc[b][3]=0;}
            #pragma unroll
            for(int ks=0;ks<8;ks++){
                int i0 = (wid*128 + ks*16)/2 + (lane&3);
                uint32_t b00 = h2[ i0   *16 + r];
                uint32_t b01 = h2[(i0+4)*16 + r];
                uint32_t b10 = h2[ i0   *16 + 8 + r];
                uint32_t b11 = h2[(i0+4)*16 + 8 + r];
                uint32_t ar[4] = {wA[ks].x, wA[ks].y, wA[ks].z, wA[ks].w};
                mma16816(acc[0], ar, b00, b01);
                mma16816(acc[1], ar, b10, b11);
            }
            #pragma unroll
            for(int bh=0;bh<2;bh++){
                red[wid][r  ][bh*8 + q    ] = acc[bh][0];
                red[wid][r  ][bh*8 + q + 1] = acc[bh][1];
                red[wid][r+8][bh*8 + q    ] = acc[bh][2];
                red[wid][r+8][bh*8 + q + 1] = acc[bh][3];
            }
            __syncthreads();
            {
                int col = tid>>4, b = tid&15;
                float s = 0.f;
                #pragma unroll
                for(int w=0;w<8;w++) s += red[w][col][b];
                if (bid < 64){
                    int c = bid*16 + col;
                    float val = s + Gt[(size_t)c*16 + b];
                    g_zT[c*16 + b] = 1.f/(1.f + expf(-val));
                } else {
                    int c = (bid-64)*16 + col;
                    float val = s + Gt[16384 + (size_t)c*16 + b];
                    float sig = 1.f/(1.f + expf(-val));
                    g_rhT[(c>>1)*32 + b*2 + (c&1)] = __float2half(sig * g_hfT[c*16 + b]);
                }
            }
        }
        gridbar(base + nb++);
        // ---------------- phase B : n (bid<64) ----------------
        if (bid < 64){
            float acc[2][4];
            #pragma unroll
            for(int b=0;b<2;b++){acc[b][0]=0;acc[b][1]=0;acc[b][2]=0;acc[b][3]=0;}
            #pragma unroll
            for(int ks=0;ks<8;ks++){
                int i0 = (wid*128 + ks*16)/2 + (lane&3);
                uint32_t b00 = rh2[ i0   *16 + r];
                uint32_t b01 = rh2[(i0+4)*16 + r];
                uint32_t b10 = rh2[ i0   *16 + 8 + r];
                uint32_t b11 = rh2[(i0+4)*16 + 8 + r];
                uint32_t ar[4] = {wB[ks].x, wB[ks].y, wB[ks].z, wB[ks].w};
                mma16816(acc[0], ar, b00, b01);
                mma16816(acc[1], ar, b10, b11);
            }
            #pragma unroll
            for(int bh=0;bh<2;bh++){
                red[wid][r  ][bh*8 + q    ] = acc[bh][0];
                red[wid][r  ][bh*8 + q + 1] = acc[bh][1];
                red[wid][r+8][bh*8 + q    ] = acc[bh][2];
                red[wid][r+8][bh*8 + q + 1] = acc[bh][3];
            }
            __syncthreads();
            {
                int col = tid>>4, b = tid&15;
                float s = 0.f;
                #pragma unroll
                for(int w=0;w<8;w++) s += red[w][col][b];
                int c = bid*16 + col;
                float val = s + Gt[32768 + (size_t)c*16 + b];
                float nv = tanhf(val);
                float z = g_zT[c*16 + b];
                float h = g_hfT[c*16 + b];
                float hn = (1.f - z)*h + z*nv;
                g_hfT[c*16 + b] = hn;
                g_hT[(c>>1)*32 + b*2 + (c&1)] = __float2half(hn);
                Hout[(size_t)(t*16 + b)*1024 + c] = __float2half(hn);
                if (t == SEQT-1 && hfin) hfin[b*1024 + c] = hn;
            }
        }
        gridbar(base + nb++);
    }
}

// ------------------------- launch -------------------------
extern "C" void kernel_launch(void* const* d_in, const int* in_sizes, int n_in,
                              void* d_out, int out_size) {
    const int*   x   = (const int*)  d_in[0];
    const float* emb = (const float*)d_in[1];
    const float* Wz  = (const float*)d_in[2];
    const float* bz  = (const float*)d_in[3];
    const float* Wr  = (const float*)d_in[4];
    const float* br  = (const float*)d_in[5];
    const float* Wn  = (const float*)d_in[6];
    const float* bn  = (const float*)d_in[7];
    const float* Wo  = (const float*)d_in[8];
    const float* bo  = (const float*)d_in[9];
    float* out = (float*)d_out;

    bool has_hfin = ((size_t)out_size >= LOGITS + 2*BATCH*STATE);
    float* hf0 = has_hfin ? out + LOGITS               : nullptr;
    float* hf1 = has_hfin ? out + LOGITS + BATCH*STATE : nullptr;

    gather_emb<<<MROWS, 256>>>(x, emb);
    wconv_gate<<<dim3(32,32,6), dim3(32,8)>>>(Wz, Wr, Wn);
    wconv_o<<<dim3(1000,32), dim3(32,8)>>>(Wo);
    repackA<<<dim3(NBLK,8,2), 256>>>(Wz, Wr);
    repackB<<<dim3(64,8,2), 256>>>(Wn);

    // layer 0
    gemm_tc<0><<<dim3(24,32), 256>>>(0, 0, bz, br, bn, nullptr);
    recur<<<NBLK, 256>>>(0, hf0);
    // layer 1
    gemm_tc<0><<<dim3(24,32), 256>>>(1, 1, bz, br, bn, nullptr);
    recur<<<NBLK, 256>>>(1, hf1);
    // projection
    gemm_tc<1><<<dim3(250,32), 256>>>(2, 0, bo, bo, bo, out);
}

// round 10
// speedup vs baseline: 2.2358x; 2.2358x over previous
#include <cuda_runtime.h>
#include <cuda_fp16.h>
#include <math.h>
#include <stdint.h>

#define BATCH 16
#define SEQT  256
#define STATE 1024
#define VOCAB 32000
#define MROWS (SEQT*BATCH)          /* 4096 */
#define LOGITS ((size_t)BATCH*SEQT*VOCAB)
#define NBLK 128

// ------------------------- static device scratch -------------------------
__device__ __half g_WxT[2*3*1024*1024];        // [(j*3+g)*1024 + c][k]  x-part W^T
__device__ __half g_WoT[(size_t)VOCAB*1024];   // [v][k]
__device__ __half g_X0 [(size_t)MROWS*1024];   // embeddings fp16, row = t*16+b
__device__ __half g_Hall[2*(size_t)MROWS*1024];// hidden states per layer, row = t*16+b
__device__ float  g_G  [(size_t)SEQT*3*BATCH*1024]; // [t][gate][c][b]
// batch-minor per-step state
__device__ float  g_hfT[1024*16];              // [c][b] fp32 h
__device__ float  g_zT [1024*16];              // [c][b]
__device__ __half g_hT [1024*16];              // word (c>>1)*16+b = (h[2k],h[2k+1]) for batch b
__device__ __half g_rhT[1024*16];              // same layout, r*h
// mma-fragment-packed recurrent weights
__device__ uint4  gFragA[(size_t)2*NBLK*8*8*32];   // [j][bid128][kh8][ks8][lane32] : z|r
__device__ uint4  gFragB[(size_t)2*64*8*8*32];     // [j][bid64][kh8][ks8][lane32] : n
// barrier state (monotonic across launches/replays) — R3-proven two-hop
__device__ volatile unsigned g_arrive[NBLK];
__device__ volatile unsigned g_release;

// ------------------------- small helpers -------------------------
__device__ __forceinline__ uint32_t smem_u32(const void* p){
    return (uint32_t)__cvta_generic_to_shared(p);
}
__device__ __forceinline__ void ldsm_x4(uint32_t* r, uint32_t a){
    asm volatile("ldmatrix.sync.aligned.m8n8.x4.shared.b16 {%0,%1,%2,%3},[%4];"
        : "=r"(r[0]),"=r"(r[1]),"=r"(r[2]),"=r"(r[3]) : "r"(a));
}
__device__ __forceinline__ void mma16816(float* c, const uint32_t* a, uint32_t b0, uint32_t b1){
    asm volatile(
      "mma.sync.aligned.m16n8k16.row.col.f32.f16.f16.f32 "
      "{%0,%1,%2,%3},{%4,%5,%6,%7},{%8,%9},{%0,%1,%2,%3};"
      : "+f"(c[0]),"+f"(c[1]),"+f"(c[2]),"+f"(c[3])
      : "r"(a[0]),"r"(a[1]),"r"(a[2]),"r"(a[3]),"r"(b0),"r"(b1));
}
__device__ __forceinline__ void cp16(void* s, const void* g){
    asm volatile("cp.async.cg.shared.global [%0],[%1],16;" :: "r"(smem_u32(s)), "l"(g));
}
#define CP_COMMIT() asm volatile("cp.async.commit_group;")
#define CP_WAIT1()  asm volatile("cp.async.wait_group 1;")
#define CP_WAIT0()  asm volatile("cp.async.wait_group 0;")

// R3-proven two-hop grid barrier (volatile scalar polls ONLY — the ld.cg
// vectorized poll variants failed correctness in R5/R8/R9).
__device__ __forceinline__ void gridbar(unsigned target){
    __syncthreads();
    if (blockIdx.x == 0){
        unsigned t = threadIdx.x;
        if (t >= 1 && t < NBLK){
            while (g_arrive[t] < target) { }
        }
        __syncthreads();
        if (t == 0){ __threadfence(); g_release = target; }
        __syncthreads();
    } else {
        if (threadIdx.x == 0){
            __threadfence();
            g_arrive[blockIdx.x] = target;
            while (g_release < target) { }
            __threadfence();
        }
        __syncthreads();
    }
}

// ------------------------- weight prep -------------------------
__global__ void wconv_gate(const float* __restrict__ Wz, const float* __restrict__ Wr,
                           const float* __restrict__ Wn){
    int jg = blockIdx.z; int g = jg % 3; int j = jg / 3;
    const float* W = (g==0?Wz:(g==1?Wr:Wn)) + (size_t)j*2048*1024;
    __shared__ float tile[32][33];
    int k0 = blockIdx.x*32, c0 = blockIdx.y*32;
    int tx = threadIdx.x, ty = threadIdx.y;
    for (int i=ty;i<32;i+=8)
        tile[i][tx] = W[(size_t)(k0+i)*1024 + c0 + tx];
    __syncthreads();
    for (int i=ty;i<32;i+=8)
        g_WxT[((size_t)(j*3+g)*1024 + c0 + i)*1024 + k0 + tx] = __float2half(tile[tx][i]);
}

__global__ void wconv_o(const float* __restrict__ Wo){
    __shared__ float tile[32][33];
    int v0 = blockIdx.x*32, k0 = blockIdx.y*32;
    int tx = threadIdx.x, ty = threadIdx.y;
    for (int i=ty;i<32;i+=8)
        tile[i][tx] = Wo[(size_t)(k0+i)*VOCAB + v0 + tx];
    __syncthreads();
    for (int i=ty;i<32;i+=8)
        g_WoT[(size_t)(v0+i)*1024 + k0 + tx] = __float2half(tile[tx][i]);
}

// h-part gate weights -> mma A-fragment order
__global__ void repackA(const float* __restrict__ Wz, const float* __restrict__ Wr){
    int bid = blockIdx.x, kh = blockIdx.y, j = blockIdx.z;
    int tid = threadIdx.x;
    int ks = tid >> 5, lane = tid & 31;
    int r = lane >> 2, q = (lane & 3)*2;
    int gate = bid >> 6;
    int n0 = (bid & 63)*16;
    const float* W = (gate ? Wr : Wz) + (size_t)j*2048*1024;
    int k0 = kh*128 + ks*16;
    size_t rb = (size_t)(1024 + k0 + q)*1024 + n0 + r;
    uint4 o; __half2 t;
    t = __floats2half2_rn(W[rb],              W[rb + 1024]);         o.x = *(uint32_t*)&t;
    t = __floats2half2_rn(W[rb + 8],          W[rb + 1024 + 8]);     o.y = *(uint32_t*)&t;
    t = __floats2half2_rn(W[rb + 8*1024],     W[rb + 9*1024]);       o.z = *(uint32_t*)&t;
    t = __floats2half2_rn(W[rb + 8*1024 + 8], W[rb + 9*1024 + 8]);   o.w = *(uint32_t*)&t;
    gFragA[((((size_t)j*NBLK + bid)*8 + kh)*8 + ks)*32 + lane] = o;
}

__global__ void repackB(const float* __restrict__ Wn){
    int bid = blockIdx.x, kh = blockIdx.y, j = blockIdx.z;
    int tid = threadIdx.x;
    int ks = tid >> 5, lane = tid & 31;
    int r = lane >> 2, q = (lane & 3)*2;
    int n0 = bid*16;
    const float* W = Wn + (size_t)j*2048*1024;
    int k0 = kh*128 + ks*16;
    size_t rb = (size_t)(1024 + k0 + q)*1024 + n0 + r;
    uint4 o; __half2 t;
    t = __floats2half2_rn(W[rb],              W[rb + 1024]);         o.x = *(uint32_t*)&t;
    t = __floats2half2_rn(W[rb + 8],          W[rb + 1024 + 8]);     o.y = *(uint32_t*)&t;
    t = __floats2half2_rn(W[rb + 8*1024],     W[rb + 9*1024]);       o.z = *(uint32_t*)&t;
    t = __floats2half2_rn(W[rb + 8*1024 + 8], W[rb + 9*1024 + 8]);   o.w = *(uint32_t*)&t;
    gFragB[((((size_t)j*64 + bid)*8 + kh)*8 + ks)*32 + lane] = o;
}

__global__ void gather_emb(const int* __restrict__ x, const float* __restrict__ emb){
    int m = blockIdx.x;                 // t*16+b
    int t = m >> 4, b = m & 15;
    int tok = x[b*SEQT + t];
    float4 v = ((const float4*)(emb + (size_t)tok*1024))[threadIdx.x];
    __half2 h0 = __floats2half2_rn(v.x, v.y);
    __half2 h1 = __floats2half2_rn(v.z, v.w);
    size_t o = (size_t)m*1024 + threadIdx.x*4;
    *(__half2*)&g_X0[o]   = h0;
    *(__half2*)&g_X0[o+2] = h1;
}

// ------------------------- tensor-core GEMM (128x128x32 tiles) -------------------------
template<int MODE>
__global__ void __launch_bounds__(256) gemm_tc(
    int asel, int jl,
    const float* __restrict__ bias0, const float* __restrict__ bias1,
    const float* __restrict__ bias2, float* __restrict__ Cext)
{
    const __half* A = (asel==0) ? g_X0 : g_Hall + (size_t)(asel-1)*MROWS*1024;
    const __half* BT = (MODE==0) ? g_WxT + (size_t)jl*3*1024*1024 : g_WoT;

    __shared__ __half As[2][128][40];
    __shared__ __half Bs[2][128][40];

    const int tid = threadIdx.x;
    const int wid = tid >> 5, lane = tid & 31;
    const int wm = wid >> 2, wn = wid & 3;
    const int bm = blockIdx.y*128, bn = blockIdx.x*128;

    float acc[4][4][4];
    #pragma unroll
    for(int a=0;a<4;a++)
      #pragma unroll
      for(int b=0;b<4;b++){acc[a][b][0]=0;acc[a][b][1]=0;acc[a][b][2]=0;acc[a][b][3]=0;}

    #define GLOAD(buf,kc) do{                                                    \
        _Pragma("unroll")                                                        \
        for(int i=0;i<2;i++){                                                    \
            int cch = tid + i*256;                                               \
            int row = cch>>2, koff=(cch&3)*8;                                    \
            cp16(&As[buf][row][koff], A  + (size_t)(bm+row)*1024 + (kc)*32 + koff); \
            cp16(&Bs[buf][row][koff], BT + (size_t)(bn+row)*1024 + (kc)*32 + koff); \
        } }while(0)

    GLOAD(0,0); CP_COMMIT();

    for (int kc=0; kc<32; kc++){
        int buf = kc & 1;
        if (kc+1 < 32){ GLOAD(buf^1, kc+1); CP_COMMIT(); CP_WAIT1(); }
        else { CP_WAIT0(); }
        __syncthreads();

        #pragma unroll
        for(int ks=0;ks<2;ks++){
            uint32_t af[4][4];
            const int g = lane >> 3;
            #pragma unroll
            for(int mt=0;mt<4;mt++){
                int rr = wm*64 + mt*16 + ((g&1)<<3) + (lane&7);
                int kk = ks*16 + ((g>>1)<<3);
                ldsm_x4(af[mt], smem_u32(&As[buf][rr][kk]));
            }
            uint32_t bf[2][4];
            #pragma unroll
            for(int bt=0;bt<2;bt++){
                int rr = wn*32 + bt*16 + ((g>>1)<<3) + (lane&7);
                int kk = ks*16 + ((g&1)<<3);
                ldsm_x4(bf[bt], smem_u32(&Bs[buf][rr][kk]));
            }
            #pragma unroll
            for(int mt=0;mt<4;mt++)
              #pragma unroll
              for(int bt=0;bt<2;bt++){
                mma16816(acc[mt][bt*2+0], af[mt], bf[bt][0], bf[bt][1]);
                mma16816(acc[mt][bt*2+1], af[mt], bf[bt][2], bf[bt][3]);
              }
        }
        __syncthreads();
    }
    #undef GLOAD

    #pragma unroll
    for(int mt=0;mt<4;mt++){
        int mbase = bm + wm*64 + mt*16 + (lane>>2);
        #pragma unroll
        for(int nt=0;nt<4;nt++){
            int n = bn + wn*32 + nt*8 + (lane&3)*2;
            #pragma unroll
            for(int half_=0;half_<2;half_++){
                int m = mbase + half_*8;
                float v0 = acc[mt][nt][half_*2+0];
                float v1 = acc[mt][nt][half_*2+1];
                int tt = m>>4, b = m&15;
                if (MODE==0){
                    int g = n>>10, c = n&1023;
                    const float* bp = (g==0)?bias0:((g==1)?bias1:bias2);
                    size_t o = (size_t)tt*49152 + (size_t)g*16384 + (size_t)c*16 + b;
                    g_G[o]    = v0 + bp[jl*1024+c];
                    g_G[o+16] = v1 + bp[jl*1024+c+1];
                } else {
                    size_t o = ((size_t)b*SEQT + tt)*VOCAB + n;
                    float2 out; out.x = v0 + bias0[n]; out.y = v1 + bias0[n+1];
                    *(float2*)&Cext[o] = out;
                }
            }
        }
    }
}

// ------------------------- persistent recurrence (one layer) -------------------------
// 128 blocks x 256 threads. Phase A: blocks 0-63 => z cols, 64-127 => r cols.
// Phase B: blocks 0-63 => n cols. Recurrent weights live in registers.
__global__ void __launch_bounds__(256) recur(int jl, float* __restrict__ hfin){
    const int tid = threadIdx.x, bid = blockIdx.x;
    const int wid = tid>>5, lane = tid&31;
    const int r = lane>>2, q = (lane&3)*2;
    __shared__ float red[8][16][17];

    unsigned base = g_release;       // stable pre-barrier; monotonic across launches
    __half* Hout = g_Hall + (size_t)jl*MROWS*1024;

    // recurrent weight fragments -> registers for the whole sequence
    const uint4* fa = gFragA + (((size_t)jl*NBLK + bid)*8 + wid)*8*32;
    uint4 wA[8];
    #pragma unroll
    for(int ks=0;ks<8;ks++) wA[ks] = fa[ks*32 + lane];
    uint4 wB[8];
    if (bid < 64){
        const uint4* fb = gFragB + (((size_t)jl*64 + bid)*8 + wid)*8*32;
        #pragma unroll
        for(int ks=0;ks<8;ks++) wB[ks] = fb[ks*32 + lane];
    }

    { int idx = bid*256 + tid;
      if (idx < 16384){ g_hfT[idx] = 0.f; g_hT[idx] = __float2half(0.f); } }
    unsigned nb = 1;
    gridbar(base + nb++);

    const uint32_t* h2  = (const uint32_t*)g_hT;
    const uint32_t* rh2 = (const uint32_t*)g_rhT;

    for (int t=0; t<SEQT; t++){
        const float* Gt = g_G + (size_t)t*49152;
        // ---------------- phase A : z (bid<64) / r (bid>=64) ----------------
        {
            float acc[2][4];
            #pragma unroll
            for(int b=0;b<2;b++){acc[b][0]=0;acc[b][1]=0;acc[b][2]=0;acc[b][3]=0;}
            #pragma unroll
            for(int ks=0;ks<8;ks++){
                int i0 = (wid*128 + ks*16)/2 + (lane&3);
                uint32_t b00 = __ldcg(&h2[ i0   *16 + r]);
                uint32_t b01 = __ldcg(&h2[(i0+4)*16 + r]);
                uint32_t b10 = __ldcg(&h2[ i0   *16 + 8 + r]);
                uint32_t b11 = __ldcg(&h2[(i0+4)*16 + 8 + r]);
                uint32_t ar[4] = {wA[ks].x, wA[ks].y, wA[ks].z, wA[ks].w};
                mma16816(acc[0], ar, b00, b01);
                mma16816(acc[1], ar, b10, b11);
            }
            #pragma unroll
            for(int bh=0;bh<2;bh++){
                red[wid][r  ][bh*8 + q    ] = acc[bh][0];
                red[wid][r  ][bh*8 + q + 1] = acc[bh][1];
                red[wid][r+8][bh*8 + q    ] = acc[bh][2];
                red[wid][r+8][bh*8 + q + 1] = acc[bh][3];
            }
            __syncthreads();
            {
                int col = tid>>4, b = tid&15;
                float s = 0.f;
                #pragma unroll
                for(int w=0;w<8;w++) s += red[w][col][b];
                if (bid < 64){
                    int c = bid*16 + col;
                    float val = s + Gt[(size_t)c*16 + b];
                    g_zT[c*16 + b] = 1.f/(1.f + expf(-val));
                } else {
                    int c = (bid-64)*16 + col;
                    float val = s + Gt[16384 + (size_t)c*16 + b];
                    float sig = 1.f/(1.f + expf(-val));
                    g_rhT[(c>>1)*32 + b*2 + (c&1)] = __float2half(sig * __ldcg(&g_hfT[c*16 + b]));
                }
            }
        }
        gridbar(base + nb++);
        // ---------------- phase B : n (bid<64) ----------------
        if (bid < 64){
            float acc[2][4];
            #pragma unroll
            for(int b=0;b<2;b++){acc[b][0]=0;acc[b][1]=0;acc[b][2]=0;acc[b][3]=0;}
            #pragma unroll
            for(int ks=0;ks<8;ks++){
                int i0 = (wid*128 + ks*16)/2 + (lane&3);
                uint32_t b00 = __ldcg(&rh2[ i0   *16 + r]);
                uint32_t b01 = __ldcg(&rh2[(i0+4)*16 + r]);
                uint32_t b10 = __ldcg(&rh2[ i0   *16 + 8 + r]);
                uint32_t b11 = __ldcg(&rh2[(i0+4)*16 + 8 + r]);
                uint32_t ar[4] = {wB[ks].x, wB[ks].y, wB[ks].z, wB[ks].w};
                mma16816(acc[0], ar, b00, b01);
                mma16816(acc[1], ar, b10, b11);
            }
            #pragma unroll
            for(int bh=0;bh<2;bh++){
                red[wid][r  ][bh*8 + q    ] = acc[bh][0];
                red[wid][r  ][bh*8 + q + 1] = acc[bh][1];
                red[wid][r+8][bh*8 + q    ] = acc[bh][2];
                red[wid][r+8][bh*8 + q + 1] = acc[bh][3];
            }
            __syncthreads();
            {
                int col = tid>>4, b = tid&15;
                float s = 0.f;
                #pragma unroll
                for(int w=0;w<8;w++) s += red[w][col][b];
                int c = bid*16 + col;
                float val = s + Gt[32768 + (size_t)c*16 + b];
                float nv = tanhf(val);
                float z = __ldcg(&g_zT[c*16 + b]);
                float h = __ldcg(&g_hfT[c*16 + b]);
                float hn = (1.f - z)*h + z*nv;
                g_hfT[c*16 + b] = hn;
                g_hT[(c>>1)*32 + b*2 + (c&1)] = __float2half(hn);
                Hout[(size_t)(t*16 + b)*1024 + c] = __float2half(hn);
                if (t == SEQT-1 && hfin) hfin[b*1024 + c] = hn;
            }
        }
        gridbar(base + nb++);
    }
}

// ------------------------- launch -------------------------
extern "C" void kernel_launch(void* const* d_in, const int* in_sizes, int n_in,
                              void* d_out, int out_size) {
    const int*   x   = (const int*)  d_in[0];
    const float* emb = (const float*)d_in[1];
    const float* Wz  = (const float*)d_in[2];
    const float* bz  = (const float*)d_in[3];
    const float* Wr  = (const float*)d_in[4];
    const float* br  = (const float*)d_in[5];
    const float* Wn  = (const float*)d_in[6];
    const float* bn  = (const float*)d_in[7];
    const float* Wo  = (const float*)d_in[8];
    const float* bo  = (const float*)d_in[9];
    float* out = (float*)d_out;

    bool has_hfin = ((size_t)out_size >= LOGITS + 2*BATCH*STATE);
    float* hf0 = has_hfin ? out + LOGITS               : nullptr;
    float* hf1 = has_hfin ? out + LOGITS + BATCH*STATE : nullptr;

    gather_emb<<<MROWS, 256>>>(x, emb);
    wconv_gate<<<dim3(32,32,6), dim3(32,8)>>>(Wz, Wr, Wn);
    wconv_o<<<dim3(1000,32), dim3(32,8)>>>(Wo);
    repackA<<<dim3(NBLK,8,2), 256>>>(Wz, Wr);
    repackB<<<dim3(64,8,2), 256>>>(Wn);

    // layer 0
    gemm_tc<0><<<dim3(24,32), 256>>>(0, 0, bz, br, bn, nullptr);
    recur<<<NBLK, 256>>>(0, hf0);
    // layer 1
    gemm_tc<0><<<dim3(24,32), 256>>>(1, 1, bz, br, bn, nullptr);
    recur<<<NBLK, 256>>>(1, hf1);
    // projection
    gemm_tc<1><<<dim3(250,32), 256>>>(2, 0, bo, bo, bo, out);
}